// round 6
// baseline (speedup 1.0000x reference)
#include <cuda_runtime.h>

// ContinuousPositionBias for GB300 — round 6 (scalarized windows, no arrays).
// Inputs: 0 glob_pos(1,32,4) f32 | 1 coords_table(2209,2) f32 | 2 rpi(unused)
//         3 W1(2,512) | 4 b1(512) | 5 W2(512,16) | 6 num_prefix_tokens(=1)
// Output: (32,16,577,577) f32

#define NT     2209
#define HEADS  16
#define DHID   512
#define BATCH  32
#define OW     577
#define PLANE  (OW*OW)    // 332929

__device__ float g_bias[BATCH * HEADS * NT];   // (b,h,t)

typedef unsigned long long u64;

__device__ __forceinline__ u64 fma2(u64 a, u64 b, u64 c) {
    u64 d;
    asm("fma.rn.f32x2 %0, %1, %2, %3;" : "=l"(d) : "l"(a), "l"(b), "l"(c));
    return d;
}
__device__ __forceinline__ u64 pack2(float x) {
    u64 d;
    asm("mov.b64 %0, {%1, %1};" : "=l"(d) : "f"(x));
    return d;
}
__device__ __forceinline__ void unpack2(u64 v, float& lo, float& hi) {
    asm("mov.b64 {%0, %1}, %2;" : "=f"(lo), "=f"(hi) : "l"(v));
}

// ---------------------------------------------------------------------------
// Kernel A: bias = relu((ctab+pos) @ W1 + b1) @ W2 — 1 t per thread, 576 blocks
// ---------------------------------------------------------------------------
__global__ __launch_bounds__(128) void mlp_kernel(
    const float* __restrict__ glob, const float* __restrict__ ctab,
    const float* __restrict__ W1,   const float* __restrict__ b1,
    const float* __restrict__ W2)
{
    __shared__ __align__(16) float4 w1s[DHID];
    __shared__ __align__(16) float  w2s[DHID * HEADS];

    const int tid = threadIdx.x;
    {
        const float4* src = (const float4*)W2;
        float4* dst = (float4*)w2s;
        #pragma unroll
        for (int k = tid; k < DHID * HEADS / 4; k += 128) dst[k] = src[k];
        for (int d = tid; d < DHID; d += 128)
            w1s[d] = make_float4(W1[d], W1[DHID + d], b1[d], 0.0f);
    }
    __syncthreads();

    const int b = blockIdx.y;
    const float g0 = glob[b*4+0], g1 = glob[b*4+1];
    const float g2 = glob[b*4+2], g3 = glob[b*4+3];
    float p0 = g2 / g0 * 8.0f;
    float p1 = g3 / g1 * 8.0f;
    p0 = copysignf(log2f(fabsf(p0) + 1.0f), p0) * (2.0f / 3.0f) - 1.0f;
    p1 = copysignf(log2f(fabsf(p1) + 1.0f), p1) * (2.0f / 3.0f) - 1.0f;

    const int t = blockIdx.x * 128 + tid;
    if (t >= NT) return;

    const float c0 = ctab[2*t]     + p0;
    const float c1 = ctab[2*t + 1] + p1;

    u64 acc0 = 0, acc1 = 0, acc2 = 0, acc3 = 0;
    u64 acc4 = 0, acc5 = 0, acc6 = 0, acc7 = 0;

    const ulonglong2* __restrict__ w2q = (const ulonglong2*)w2s;

    #pragma unroll 4
    for (int d = 0; d < DHID; d++) {
        const float4 w = w1s[d];
        const float hd = fmaxf(fmaf(c0, w.x, fmaf(c1, w.y, w.z)), 0.0f);
        const u64 hd2 = pack2(hd);
        const ulonglong2 q0 = w2q[d*4 + 0];
        const ulonglong2 q1 = w2q[d*4 + 1];
        const ulonglong2 q2 = w2q[d*4 + 2];
        const ulonglong2 q3 = w2q[d*4 + 3];
        acc0 = fma2(hd2, q0.x, acc0);
        acc1 = fma2(hd2, q0.y, acc1);
        acc2 = fma2(hd2, q1.x, acc2);
        acc3 = fma2(hd2, q1.y, acc3);
        acc4 = fma2(hd2, q2.x, acc4);
        acc5 = fma2(hd2, q2.y, acc5);
        acc6 = fma2(hd2, q3.x, acc6);
        acc7 = fma2(hd2, q3.y, acc7);
    }

    float* outb = g_bias + (size_t)b * (HEADS * NT) + t;
    float lo, hi;
    unpack2(acc0, lo, hi); outb[ 0*NT] = lo; outb[ 1*NT] = hi;
    unpack2(acc1, lo, hi); outb[ 2*NT] = lo; outb[ 3*NT] = hi;
    unpack2(acc2, lo, hi); outb[ 4*NT] = lo; outb[ 5*NT] = hi;
    unpack2(acc3, lo, hi); outb[ 6*NT] = lo; outb[ 7*NT] = hi;
    unpack2(acc4, lo, hi); outb[ 8*NT] = lo; outb[ 9*NT] = hi;
    unpack2(acc5, lo, hi); outb[10*NT] = lo; outb[11*NT] = hi;
    unpack2(acc6, lo, hi); outb[12*NT] = lo; outb[13*NT] = hi;
    unpack2(acc7, lo, hi); outb[14*NT] = lo; outb[15*NT] = hi;
}

// ---------------------------------------------------------------------------
// Kernel B — diagonal-window scatter, 4x4 tiles, fully scalarized.
//   val(r=1+24ib+ii, c>=1) = rev[(23-ii) + f(c)],  f(c)=(c-1)+23*((c-1)/24)
// Main window wv0..wv9 at A-6; crossing window wc0..wc4 at (m0<=2 ? A-29 : A+22).
// ---------------------------------------------------------------------------
#define FRONT 32
#define SHW(a) sh[(a) + ((a) >> 2)]

__global__ __launch_bounds__(192) void scatter_kernel(float* __restrict__ out)
{
    __shared__ float sh[1536];
    const int tid   = threadIdx.x;
    const int ib    = blockIdx.x;     // 0..23 bands, 24 = zero-row writer
    const int plane = blockIdx.y;     // 0..511
    float* __restrict__ pb = out + (size_t)plane * PLANE;

    if (ib == 24) {                   // row 0 is all zeros
        for (int c = tid; c < OW; c += 192) pb[c] = 0.0f;
        return;
    }

    // stage reversed + padded (phys = a + a>>2)
    const float* __restrict__ bp = g_bias + (size_t)plane * NT + 47 * ib;
    for (int u = tid; u < 1128; u += 192) {
        int a = (1127 - u) + FRONT;
        SHW(a) = bp[u];
    }
    __syncthreads();

    const int w     = tid >> 5;
    const int lane  = tid & 31;
    const int ii0   = 4 * w;
    const int r0    = 1 + 24 * ib + ii0;
    const int basev = 23 - ii0;
    const int alpha = (int)(((size_t)plane * PLANE + (size_t)r0 * OW) & 3);
    const int cs    = (4 - alpha) & 3;          // first aligned col for di=0
    float* __restrict__ rp = pb + (size_t)r0 * OW;

    for (int t = 0; t < 5; t++) {
        const int k = lane + 32 * t;
        if (k > 144) continue;
        const int cbase = cs + 4 * k;

        if (cbase >= 4 && cbase <= 573) {
            const int j0 = cbase - 1;
            const int q0 = (j0 * 2731) >> 16;       // j0 / 24
            const int m0 = j0 - 24 * q0;
            const int A  = basev + j0 + 23 * q0 + FRONT;

            const float wv0 = SHW(A-6), wv1 = SHW(A-5), wv2 = SHW(A-4),
                        wv3 = SHW(A-3), wv4 = SHW(A-2), wv5 = SHW(A-1),
                        wv6 = SHW(A),   wv7 = SHW(A+1), wv8 = SHW(A+2),
                        wv9 = SHW(A+3);
            const int aC = (m0 <= 2) ? (A - 29) : (A + 22);
            const float wc0 = SHW(aC),   wc1 = SHW(aC+1), wc2 = SHW(aC+2),
                        wc3 = SHW(aC+3), wc4 = SHW(aC+4);

            const bool p21 = (m0 >= 21), p22 = (m0 >= 22), p23 = (m0 >= 23);
            const bool b0  = (m0 == 0),  b1  = (m0 <= 1),  b2  = (m0 <= 2);

            const float4 v0 = make_float4(wv6,
                                          p23 ? wc2 : wv7,
                                          p22 ? wc3 : wv8,
                                          p21 ? wc4 : wv9);
            const float4 v1 = make_float4(b0  ? wc4 : wv4,
                                          wv5,
                                          p23 ? wc1 : wv6,
                                          p22 ? wc2 : wv7);
            const float4 v2 = make_float4(b1  ? wc2 : wv2,
                                          b0  ? wc3 : wv3,
                                          wv4,
                                          p23 ? wc0 : wv5);
            const float4 v3 = make_float4(b2  ? wc0 : wv0,
                                          b1  ? wc1 : wv1,
                                          b0  ? wc2 : wv2,
                                          wv3);

            *(float4*)(rp + 0*OW + cbase)     = v0;
            *(float4*)(rp + 1*OW + cbase - 1) = v1;
            *(float4*)(rp + 2*OW + cbase - 2) = v2;
            *(float4*)(rp + 3*OW + cbase - 3) = v3;
        } else {
            // ---- edge path: scalar
            #pragma unroll
            for (int di = 0; di < 4; di++) {
                int clo = (k == 0) ? 0 : (cbase - di);
                int chi = cbase - di + 3;
                if (chi > 576) chi = 576;
                for (int c = clo; c <= chi; c++) {
                    float val = 0.0f;
                    if (c >= 1) {
                        const int j = c - 1;
                        const int q = (j * 2731) >> 16;
                        const int a = basev - di + j + 23 * q + FRONT;
                        val = SHW(a);
                    }
                    rp[di * OW + c] = val;
                }
            }
        }
    }
}

// ---------------------------------------------------------------------------
extern "C" void kernel_launch(void* const* d_in, const int* in_sizes, int n_in,
                              void* d_out, int out_size)
{
    const float* glob = (const float*)d_in[0];
    const float* ctab = (const float*)d_in[1];
    const float* W1   = (const float*)d_in[3];
    const float* b1   = (const float*)d_in[4];
    const float* W2   = (const float*)d_in[5];
    float* out        = (float*)d_out;

    mlp_kernel<<<dim3(18, BATCH), 128>>>(glob, ctab, W1, b1, W2);
    scatter_kernel<<<dim3(25, BATCH * HEADS), 192>>>(out);
}

// round 7
// speedup vs baseline: 1.0857x; 1.0857x over previous
#include <cuda_runtime.h>

// ContinuousPositionBias for GB300 — round 7 (scatter = round-5 frozen; MLP 4t single-wave).
// Inputs: 0 glob_pos(1,32,4) f32 | 1 coords_table(2209,2) f32 | 2 rpi(unused)
//         3 W1(2,512) | 4 b1(512) | 5 W2(512,16) | 6 num_prefix_tokens(=1)
// Output: (32,16,577,577) f32

#define NT     2209
#define HEADS  16
#define DHID   512
#define BATCH  32
#define OW     577
#define PLANE  (OW*OW)    // 332929
#define TOTT   (BATCH * NT)   // 70688

__device__ float g_bias[BATCH * HEADS * NT];   // (b,h,t)

typedef unsigned long long u64;

__device__ __forceinline__ u64 fma2(u64 a, u64 b, u64 c) {
    u64 d;
    asm("fma.rn.f32x2 %0, %1, %2, %3;" : "=l"(d) : "l"(a), "l"(b), "l"(c));
    return d;
}
__device__ __forceinline__ u64 pack2(float x) {
    u64 d;
    asm("mov.b64 %0, {%1, %1};" : "=l"(d) : "f"(x));
    return d;
}
__device__ __forceinline__ void unpack2(u64 v, float& lo, float& hi) {
    asm("mov.b64 {%0, %1}, %2;" : "=f"(lo), "=f"(hi) : "l"(v));
}

// ---------------------------------------------------------------------------
// Kernel A: bias = relu((ctab+pos) @ W1 + b1) @ W2
// 4 (b,t) pairs per thread, flat grid: 139 blocks x 128 thr = single wave.
// ---------------------------------------------------------------------------
__global__ __launch_bounds__(128) void mlp_kernel(
    const float* __restrict__ glob, const float* __restrict__ ctab,
    const float* __restrict__ W1,   const float* __restrict__ b1,
    const float* __restrict__ W2)
{
    __shared__ __align__(16) float4 w1s[DHID];
    __shared__ __align__(16) float  w2s[DHID * HEADS];

    const int tid = threadIdx.x;
    {
        const float4* src = (const float4*)W2;
        float4* dst = (float4*)w2s;
        #pragma unroll
        for (int k = tid; k < DHID * HEADS / 4; k += 128) dst[k] = src[k];
        for (int d = tid; d < DHID; d += 128)
            w1s[d] = make_float4(W1[d], W1[DHID + d], b1[d], 0.0f);
    }
    __syncthreads();

    int  bj[4], tj[4];
    bool vj[4];
    float c0j[4], c1j[4];

    #pragma unroll
    for (int j = 0; j < 4; j++) {
        const int flat = blockIdx.x * 512 + 128 * j + tid;
        vj[j] = (flat < TOTT);
        int b = 0, t = 0;
        float c0 = 0.f, c1 = 0.f;
        if (vj[j]) {
            b = flat / NT;
            t = flat - b * NT;
            const float g0 = glob[b*4+0], g1 = glob[b*4+1];
            const float g2 = glob[b*4+2], g3 = glob[b*4+3];
            float p0 = g2 / g0 * 8.0f;
            float p1 = g3 / g1 * 8.0f;
            p0 = copysignf(log2f(fabsf(p0) + 1.0f), p0) * (2.0f / 3.0f) - 1.0f;
            p1 = copysignf(log2f(fabsf(p1) + 1.0f), p1) * (2.0f / 3.0f) - 1.0f;
            c0 = ctab[2*t]   + p0;
            c1 = ctab[2*t+1] + p1;
        }
        bj[j] = b; tj[j] = t; c0j[j] = c0; c1j[j] = c1;
    }

    u64 acc[4][8];
    #pragma unroll
    for (int j = 0; j < 4; j++)
        #pragma unroll
        for (int k = 0; k < 8; k++) acc[j][k] = 0ull;

    const ulonglong2* __restrict__ w2q = (const ulonglong2*)w2s;

    #pragma unroll 2
    for (int d = 0; d < DHID; d++) {
        const float4 w = w1s[d];
        const ulonglong2 q0 = w2q[d*4 + 0];
        const ulonglong2 q1 = w2q[d*4 + 1];
        const ulonglong2 q2 = w2q[d*4 + 2];
        const ulonglong2 q3 = w2q[d*4 + 3];
        #pragma unroll
        for (int j = 0; j < 4; j++) {
            const float hd = fmaxf(fmaf(c0j[j], w.x, fmaf(c1j[j], w.y, w.z)), 0.0f);
            const u64 hd2 = pack2(hd);
            acc[j][0] = fma2(hd2, q0.x, acc[j][0]);
            acc[j][1] = fma2(hd2, q0.y, acc[j][1]);
            acc[j][2] = fma2(hd2, q1.x, acc[j][2]);
            acc[j][3] = fma2(hd2, q1.y, acc[j][3]);
            acc[j][4] = fma2(hd2, q2.x, acc[j][4]);
            acc[j][5] = fma2(hd2, q2.y, acc[j][5]);
            acc[j][6] = fma2(hd2, q3.x, acc[j][6]);
            acc[j][7] = fma2(hd2, q3.y, acc[j][7]);
        }
    }

    #pragma unroll
    for (int j = 0; j < 4; j++) {
        if (!vj[j]) continue;
        float* outb = g_bias + (size_t)bj[j] * (HEADS * NT) + tj[j];
        #pragma unroll
        for (int k = 0; k < 8; k++) {
            float lo, hi; unpack2(acc[j][k], lo, hi);
            outb[(2*k)   * NT] = lo;
            outb[(2*k+1) * NT] = hi;
        }
    }
}

// ---------------------------------------------------------------------------
// Kernel B — diagonal-window scatter (round-5, frozen).
//   val(r=1+24ib+ii, c>=1) = rev[(23-ii) + f(c)],  f(c)=(c-1)+23*((c-1)/24)
// ---------------------------------------------------------------------------
#define FRONT 32

__global__ __launch_bounds__(192) void scatter_kernel(float* __restrict__ out)
{
    __shared__ float sh[1536];
    const int tid   = threadIdx.x;
    const int ib    = blockIdx.x;     // 0..23 bands, 24 = zero-row writer
    const int plane = blockIdx.y;     // 0..511
    float* __restrict__ pb = out + (size_t)plane * PLANE;

    if (ib == 24) {                   // row 0 is all zeros
        for (int c = tid; c < OW; c += 192) pb[c] = 0.0f;
        return;
    }

    const float* __restrict__ bp = g_bias + (size_t)plane * NT + 47 * ib;
    for (int u = tid; u < 1128; u += 192) {
        int a = (1127 - u) + FRONT;
        sh[a + (a >> 2)] = bp[u];
    }
    __syncthreads();

    const int w     = tid >> 5;
    const int lane  = tid & 31;
    const int ii0   = 4 * w;
    const int r0    = 1 + 24 * ib + ii0;
    const int basev = 23 - ii0;
    const int alpha = (int)(((size_t)plane * PLANE + (size_t)r0 * OW) & 3);
    const int cs    = (4 - alpha) & 3;
    float* __restrict__ rp = pb + (size_t)r0 * OW;

    for (int t = 0; t < 5; t++) {
        const int k = lane + 32 * t;
        if (k > 144) continue;
        const int cbase = cs + 4 * k;

        if (cbase >= 4 && cbase <= 573) {
            const int j0 = cbase - 1;
            const int q0 = (j0 * 2731) >> 16;
            const int m0 = j0 - 24 * q0;
            const int A  = basev + j0 + 23 * q0 + FRONT;

            float wv[10], wc5[5];
            {
                const int aW = A - 6;
                #pragma unroll
                for (int i = 0; i < 10; i++) { int a = aW + i; wv[i] = sh[a + (a >> 2)]; }
                const int aC = (m0 <= 2) ? (A - 29) : (A + 22);
                #pragma unroll
                for (int i = 0; i < 5; i++) { int a = aC + i; wc5[i] = sh[a + (a >> 2)]; }
            }

            #pragma unroll
            for (int di = 0; di < 4; di++) {
                float4 v;
                float* vv = (float*)&v;
                #pragma unroll
                for (int e = 0; e < 4; e++) {
                    const int x   = e - di;
                    const int idx = e - 2 * di + 6;
                    if (x > 0) {
                        vv[e] = (m0 >= 24 - x) ? wc5[idx - 5] : wv[idx];
                    } else if (x < 0) {
                        vv[e] = (m0 <  -x)     ? wc5[idx]     : wv[idx];
                    } else {
                        vv[e] = wv[idx];
                    }
                }
                *(float4*)(rp + di * OW + (cbase - di)) = v;
            }
        } else {
            #pragma unroll
            for (int di = 0; di < 4; di++) {
                int clo = (k == 0) ? 0 : (cbase - di);
                int chi = cbase - di + 3;
                if (chi > 576) chi = 576;
                for (int c = clo; c <= chi; c++) {
                    float val = 0.0f;
                    if (c >= 1) {
                        const int j = c - 1;
                        const int q = (j * 2731) >> 16;
                        const int a = basev - di + j + 23 * q + FRONT;
                        val = sh[a + (a >> 2)];
                    }
                    rp[di * OW + c] = val;
                }
            }
        }
    }
}

// ---------------------------------------------------------------------------
extern "C" void kernel_launch(void* const* d_in, const int* in_sizes, int n_in,
                              void* d_out, int out_size)
{
    const float* glob = (const float*)d_in[0];
    const float* ctab = (const float*)d_in[1];
    const float* W1   = (const float*)d_in[3];
    const float* b1   = (const float*)d_in[4];
    const float* W2   = (const float*)d_in[5];
    float* out        = (float*)d_out;

    mlp_kernel<<<dim3((TOTT + 511) / 512), 128>>>(glob, ctab, W1, b1, W2);
    scatter_kernel<<<dim3(25, BATCH * HEADS), 192>>>(out);
}